// round 15
// baseline (speedup 1.0000x reference)
#include <cuda_runtime.h>
#include <math.h>

#define NB 32      // batch
#define NT 400     // timesteps
#define NU 400     // LSTM units
#define NKG 10     // attention gaussians
#define NC 73      // alphabet
#define NUC 50     // char positions
#define NO 121     // MDN outputs
#define H4 1600    // 4*NU
#define NCTA 150
#define NTH 256
#define NWARP 8
#define SLOT 32

// smem layout (float offsets)
#define OFF_CAT  0        // 15232: staged concatenated state [x(96)|w(2336)|h(12800)]
#define OFF_RED  15232    // 8192: K-split partial reduction
#define OFF_ATT  23424    // 608: attention scatter scratch
// weights
#define OFF_P0   24032    // A: 8*476*4 = 15232
#define OFF_P1H  39264    // A: 8*400*4 = 12800
#define OFF_P1W  52064    // A: 8*73*4 = 2336   (A end 54400)
#define OFF_PR   24032    // B/C: 8*403*4 = 12896
#define OFF_P2WH 36928    // B/C: 4*473*4 = 7568
#define OFF_WATT 44496    // C att: 400*30 = 12000 (end 56496)
#define SMEM_FLOATS 56496
#define SMEM_BYTES (SMEM_FLOATS*4)   // 225984

typedef unsigned long long ull;

// ---------------- packed weights (gate-interleaved float4 per (u,k)) ----------------
__device__ float4 d_P0  [NU*476];
__device__ float4 d_P1r [NU*403];
__device__ float4 d_P1h [NU*400];
__device__ float4 d_P1w [NU*73];
__device__ float4 d_P2r [NU*403];
__device__ float4 d_P2wh[NU*473];

// ---------------- double-buffered state [parity][u*NB+b] ----------------
__device__ float d_h1 [2][NU*NB];
__device__ float d_h2b[2][NU*NB];
__device__ float d_h3b[2][NU*NB];
__device__ float d_wTb[2][NC*NB];
__device__ float d_Z2pb[2][NU*4*NB];
__device__ float d_R3pb[2][NU*4*NB];
__device__ float d_h3all[NT*NU*NB];

// ---------------- versioned flags (padded) ----------------
__device__ unsigned d_fh1[50*SLOT];
__device__ unsigned d_fw [4*SLOT];
__device__ unsigned d_fh2[50*SLOT];
__device__ unsigned d_fz [50*SLOT];
__device__ unsigned d_fr [50*SLOT];
__device__ unsigned d_fh3[100*SLOT];

// =====================================================================
// pack kernel
// =====================================================================
__global__ void pack_kernel(const float* __restrict__ Wx0, const float* __restrict__ Wh0,
                            const float* __restrict__ Wx1, const float* __restrict__ Wh1,
                            const float* __restrict__ Wx2, const float* __restrict__ Wh2)
{
    int idx = blockIdx.x * blockDim.x + threadIdx.x;
    int str = gridDim.x * blockDim.x;

    for (int e = idx; e < 50*SLOT; e += str) {
        d_fh1[e]=0u; d_fh2[e]=0u; d_fz[e]=0u; d_fr[e]=0u;
    }
    for (int e = idx; e < 100*SLOT; e += str) d_fh3[e] = 0u;
    for (int e = idx; e < 4*SLOT; e += str) d_fw[e] = 0u;
    for (int e = idx; e < NU*NB; e += str) {
        d_h1[0][e]=0.f; d_h1[1][e]=0.f; d_h2b[0][e]=0.f; d_h2b[1][e]=0.f;
        d_h3b[0][e]=0.f; d_h3b[1][e]=0.f;
    }
    for (int e = idx; e < NC*NB; e += str) { d_wTb[0][e]=0.f; d_wTb[1][e]=0.f; }

    for (int e = idx; e < NU*476; e += str) {
        int u = e / 476, k = e - u*476;
        const float* s = (k < 76) ? (Wx0 + k*H4) : (Wh0 + (k-76)*H4);
        d_P0[e] = make_float4(s[u], s[NU+u], s[2*NU+u], s[3*NU+u]);
    }
    for (int e = idx; e < NU*403; e += str) {
        int u = e / 403, k = e - u*403;
        const float* s = (k < 3) ? (Wx1 + k*H4) : (Wh1 + (k-3)*H4);
        d_P1r[e] = make_float4(s[u], s[NU+u], s[2*NU+u], s[3*NU+u]);
    }
    for (int e = idx; e < NU*400; e += str) {
        int u = e / 400, k = e - u*400;
        const float* s = Wx1 + (76+k)*H4;
        d_P1h[e] = make_float4(s[u], s[NU+u], s[2*NU+u], s[3*NU+u]);
    }
    for (int e = idx; e < NU*73; e += str) {
        int u = e / 73, k = e - u*73;
        const float* s = Wx1 + (3+k)*H4;
        d_P1w[e] = make_float4(s[u], s[NU+u], s[2*NU+u], s[3*NU+u]);
    }
    for (int e = idx; e < NU*403; e += str) {
        int u = e / 403, k = e - u*403;
        const float* s = (k < 3) ? (Wx2 + k*H4) : (Wh2 + (k-3)*H4);
        d_P2r[e] = make_float4(s[u], s[NU+u], s[2*NU+u], s[3*NU+u]);
    }
    for (int e = idx; e < NU*473; e += str) {
        int u = e / 473, k = e - u*473;
        const float* s = Wx2 + (3+k)*H4;
        d_P2wh[e] = make_float4(s[u], s[NU+u], s[2*NU+u], s[3*NU+u]);
    }
}

// =====================================================================
// helpers
// =====================================================================
__device__ __forceinline__ float sigf(float x) { return 1.f / (1.f + expf(-x)); }

__device__ __forceinline__ ull pk2(float v) {
    ull r; asm("mov.b64 %0, {%1, %1};" : "=l"(r) : "f"(v)); return r;
}
__device__ __forceinline__ void upk(ull v, float& lo, float& hi) {
    asm("mov.b64 {%0, %1}, %2;" : "=f"(lo), "=f"(hi) : "l"(v));
}
__device__ __forceinline__ void fma2(ull& d, ull a, ull b) {
    asm("fma.rn.f32x2 %0, %1, %2, %0;" : "+l"(d) : "l"(a), "l"(b));
}

__device__ __forceinline__ void st_rel(unsigned* p, unsigned v) {
    asm volatile("{ .reg .u64 a; cvta.to.global.u64 a, %0; st.release.gpu.global.u32 [a], %1; }"
                 :: "l"(p), "r"(v) : "memory");
}
__device__ __forceinline__ unsigned ld_rlx(const unsigned* p) {
    unsigned v;
    asm volatile("{ .reg .u64 a; cvta.to.global.u64 a, %1; ld.relaxed.gpu.global.u32 %0, [a]; }"
                 : "=r"(v) : "l"(p) : "memory");
    return v;
}
__device__ __forceinline__ void spin_ge(const unsigned* p, unsigned r) {
    while (ld_rlx(p) < r) { }
}

// staging copy: cp.async.cg — L1 bypass global->shared
__device__ __forceinline__ void copy4(float* dst, const float* src, int nfl)
{
    unsigned base = (unsigned)__cvta_generic_to_shared(dst);
    int n4 = nfl >> 2;
    for (int i = threadIdx.x; i < n4; i += NTH) {
        asm volatile("cp.async.cg.shared.global [%0], [%1], 16;"
                     :: "r"(base + i*16), "l"((const char*)src + i*16) : "memory");
    }
}
__device__ __forceinline__ void cpwait()
{
    asm volatile("cp.async.commit_group;" ::: "memory");
    asm volatile("cp.async.wait_group 0;" ::: "memory");
    __syncthreads();
}

// K-transposed accumulate, USTR compile-time so u*USTR folds into LDS immediates
template<int USTR>
__device__ __forceinline__ void accT8(ull a01[8], ull a23[8],
                                      unsigned wbyte, unsigned vbyte, int k0, int k1, int b)
{
    unsigned va = vbyte + b*4 + k0*(NB*4);
    unsigned wa = wbyte + k0*16;
#pragma unroll 2
    for (int k = k0; k < k1; k++) {
        float hv;
        asm("ld.shared.b32 %0, [%1];" : "=f"(hv) : "r"(va));
        ull hh = pk2(hv);
#pragma unroll
        for (int u = 0; u < 8; u++) {
            ull wx, wy;
            asm("ld.shared.v2.b64 {%0,%1}, [%2];" : "=l"(wx), "=l"(wy) : "r"(wa + u*USTR));
            fma2(a01[u], wx, hh);
            fma2(a23[u], wy, hh);
        }
        va += NB*4; wa += 16;
    }
}

template<int USTR>
__device__ __forceinline__ void accT4(ull a01[4], ull a23[4],
                                      unsigned wbyte, unsigned vbyte, int k0, int k1, int b)
{
    unsigned va = vbyte + b*4 + k0*(NB*4);
    unsigned wa = wbyte + k0*16;
#pragma unroll 2
    for (int k = k0; k < k1; k++) {
        float hv;
        asm("ld.shared.b32 %0, [%1];" : "=f"(hv) : "r"(va));
        ull hh = pk2(hv);
#pragma unroll
        for (int u = 0; u < 4; u++) {
            ull wx, wy;
            asm("ld.shared.v2.b64 {%0,%1}, [%2];" : "=l"(wx), "=l"(wy) : "r"(wa + u*USTR));
            fma2(a01[u], wx, hh);
            fma2(a23[u], wy, hh);
        }
        va += NB*4; wa += 16;
    }
}

__device__ __forceinline__ void store_red8(float* s_red, int wib, int b,
                                           const ull a01[8], const ull a23[8])
{
    float* rp = s_red + wib*1024 + b;
#pragma unroll
    for (int u = 0; u < 8; u++) {
        float gi,gf,gg,go;
        upk(a01[u], gi, gf); upk(a23[u], gg, go);
        rp[u*128+0]=gi; rp[u*128+32]=gf; rp[u*128+64]=gg; rp[u*128+96]=go;
    }
}
__device__ __forceinline__ void store_red4(float* s_red, int wib, int b,
                                           const ull a01[4], const ull a23[4])
{
    float* rp = s_red + wib*512 + b;
#pragma unroll
    for (int u = 0; u < 4; u++) {
        float gi,gf,gg,go;
        upk(a01[u], gi, gf); upk(a23[u], gg, go);
        rp[u*128+0]=gi; rp[u*128+32]=gf; rp[u*128+64]=gg; rp[u*128+96]=go;
    }
}

__device__ __forceinline__ float red_sum(const float* s_red, int wstr, int us, int goff, int b)
{
    float s = 0.f;
#pragma unroll
    for (int w = 0; w < 8; w++) s += s_red[w*wstr + us*128 + goff + b];
    return s;
}

// =====================================================================
// persistent RNN kernel
// =====================================================================
__global__ void __launch_bounds__(NTH, 1)
rnn_kernel(const float* __restrict__ strokes,
           const int*   __restrict__ chars,
           const int*   __restrict__ lens,
           const float* __restrict__ b0, const float* __restrict__ p0,
           const float* __restrict__ b1, const float* __restrict__ p1,
           const float* __restrict__ b2, const float* __restrict__ p2,
           const float* __restrict__ Watt, const float* __restrict__ batt,
           const float* __restrict__ Wmdn, const float* __restrict__ bmdn,
           float* __restrict__ out)
{
    extern __shared__ float smem[];
    float* s_cat  = smem + OFF_CAT;
    float* s_red  = smem + OFF_RED;
    float* s_att  = smem + OFF_ATT;
    float* s_watt = smem + OFF_WATT;
    const unsigned sb = (unsigned)__cvta_generic_to_shared(smem);

    const int cta  = blockIdx.x;
    const int tid  = threadIdx.x;
    const int lane = tid & 31;
    const int wib  = tid >> 5;
    const int b    = lane;
    const unsigned FULL = 0xffffffffu;

    // ---- preload weight slices ----
    if (cta < 50) {
        copy4(smem + OFF_P0,  (const float*)(d_P0  + cta*8*476), 8*476*4);
        copy4(smem + OFF_P1H, (const float*)(d_P1h + cta*8*400), 8*400*4);
        copy4(smem + OFF_P1W, (const float*)(d_P1w + cta*8*73),  8*73*4);
    } else {
        const float4* prsrc = (cta < 100) ? (d_P1r + (cta-50)*8*403)
                                          : (d_P2r + (cta-100)*8*403);
        copy4(smem + OFF_PR,   (const float*)prsrc, 8*403*4);
        copy4(smem + OFF_P2WH, (const float*)(d_P2wh + (cta-50)*4*473), 4*473*4);
        if (cta >= 100 && cta < 104) copy4(s_watt, Watt, NU*30);
    }
    cpwait();
    if (cta < 50) {     // A: zero cat once (w[-1]=h1[-1]=0 for t=0's S1)
        for (int i = tid; i < 15232; i += NTH) s_cat[i] = 0.f;
        __syncthreads();
    }

    float c1reg = 0.f, c2reg = 0.f;  // A: unit = cta*8+wib
    float c3reg = 0.f;               // S4 CTAs (>=50), wib<4: unit = (cta-50)*4+wib
    float kapreg = 0.f;              // att CTAs 100-103

    for (int t = 0; t < NT; t++) {
        const int p = t & 1, q = p ^ 1;
        const unsigned rt = (unsigned)t, rt1 = (unsigned)(t+1);

        if (cta < 50) {
            // ================= A: S1 — no spins, no copies (cat reused) ========
            if (tid < 96) s_cat[tid] = __ldg(strokes + ((tid & 31)*NT + t)*3 + (tid >> 5));
            __syncthreads();
            {
                ull a01[8] = {0,0,0,0,0,0,0,0}, a23[8] = {0,0,0,0,0,0,0,0};
                int k0 = (476*wib) >> 3, k1 = (476*(wib+1)) >> 3;
                accT8<476*16>(a01, a23, sb + OFF_P0*4, sb + OFF_CAT*4, k0, k1, b);
                store_red8(s_red, wib, b, a01, a23);
            }
            __syncthreads();
            {
                int uu = cta*8 + wib;
                float zi = __ldg(b0+uu)      + red_sum(s_red, 1024, wib, 0,  b);
                float zf = __ldg(b0+NU+uu)   + red_sum(s_red, 1024, wib, 32, b);
                float zg = __ldg(b0+2*NU+uu) + red_sum(s_red, 1024, wib, 64, b);
                float zo = __ldg(b0+3*NU+uu) + red_sum(s_red, 1024, wib, 96, b);
                float ig = sigf(zi + __ldg(p0+uu)      * c1reg);
                float fg = sigf(zf + __ldg(p0+NU+uu)   * c1reg);
                float cn = fg*c1reg + ig*tanhf(zg);
                float og = sigf(zo + __ldg(p0+2*NU+uu) * cn);
                c1reg = cn;
                __stcg(&d_h1[p][uu*NB + b], og * tanhf(cn));
            }
            __syncthreads();
            if (tid == 0) st_rel(d_fh1 + cta*SLOT, rt1);

            // ================= A: S2/3 (stages into cat for next S1) ===========
            if (tid < 50) spin_ge(d_fh1 + tid*SLOT, rt1);
            else if (tid >= 64 && tid < 114) spin_ge(d_fz + (tid-64)*SLOT, rt1);
            __syncthreads();
            copy4(s_cat + 2432, d_h1[p], NU*NB);     // h1[t] -> cat h-section
            cpwait();
            {
                ull a01[8] = {0,0,0,0,0,0,0,0}, a23[8] = {0,0,0,0,0,0,0,0};
                int k0 = wib*50, k1 = k0 + 50;
                accT8<400*16>(a01, a23, sb + OFF_P1H*4, sb + (OFF_CAT+2432)*4, k0, k1, b);
                if (tid < 4) spin_ge(d_fw + tid*SLOT, rt1);
                __syncthreads();
                copy4(s_cat + 96, d_wTb[p], NC*NB);  // w[t] -> cat w-section
                cpwait();
                int kw0 = (73*wib) >> 3, kw1 = (73*(wib+1)) >> 3;
                accT8<73*16>(a01, a23, sb + OFF_P1W*4, sb + (OFF_CAT+96)*4, kw0, kw1, b);
                store_red8(s_red, wib, b, a01, a23);
            }
            __syncthreads();
            {
                int uu = cta*8 + wib;
                const float* zp = d_Z2pb[p] + uu*128 + b;
                float zi = __ldcg(zp)    + red_sum(s_red, 1024, wib, 0,  b);
                float zf = __ldcg(zp+32) + red_sum(s_red, 1024, wib, 32, b);
                float zg = __ldcg(zp+64) + red_sum(s_red, 1024, wib, 64, b);
                float zo = __ldcg(zp+96) + red_sum(s_red, 1024, wib, 96, b);
                float ig = sigf(zi + __ldg(p1+uu)      * c2reg);
                float fg = sigf(zf + __ldg(p1+NU+uu)   * c2reg);
                float cn = fg*c2reg + ig*tanhf(zg);
                float og = sigf(zo + __ldg(p1+2*NU+uu) * cn);
                c2reg = cn;
                __stcg(&d_h2b[p][uu*NB + b], og * tanhf(cn));
            }
            __syncthreads();
            if (tid == 0) st_rel(d_fh2 + cta*SLOT, rt1);
        } else {
            if (cta < 100) {
                // ================= B: R2 =================
                if (tid < 50) spin_ge(d_fh2 + tid*SLOT, rt);
                __syncthreads();
                if (tid < 96) s_cat[tid] = __ldg(strokes + ((tid & 31)*NT + t)*3 + (tid >> 5));
                copy4(s_cat + 96, d_h2b[q], NU*NB);
                cpwait();
                {
                    ull a01[8] = {0,0,0,0,0,0,0,0}, a23[8] = {0,0,0,0,0,0,0,0};
                    int k0 = (403*wib) >> 3, k1 = (403*(wib+1)) >> 3;
                    accT8<403*16>(a01, a23, sb + OFF_PR*4, sb + OFF_CAT*4, k0, k1, b);
                    store_red8(s_red, wib, b, a01, a23);
                }
                __syncthreads();
                {
                    int uu = (cta-50)*8 + wib;
                    float* dp = d_Z2pb[p] + uu*128 + b;
                    __stcg(dp+0,  __ldg(b1+uu)      + red_sum(s_red, 1024, wib, 0,  b));
                    __stcg(dp+32, __ldg(b1+NU+uu)   + red_sum(s_red, 1024, wib, 32, b));
                    __stcg(dp+64, __ldg(b1+2*NU+uu) + red_sum(s_red, 1024, wib, 64, b));
                    __stcg(dp+96, __ldg(b1+3*NU+uu) + red_sum(s_red, 1024, wib, 96, b));
                }
                __syncthreads();
                if (tid == 0) st_rel(d_fz + (cta-50)*SLOT, rt1);
            } else {
                // ================= C: R3 =================
                if (tid < 100) spin_ge(d_fh3 + tid*SLOT, rt);
                __syncthreads();
                if (tid < 96) s_cat[tid] = __ldg(strokes + ((tid & 31)*NT + t)*3 + (tid >> 5));
                copy4(s_cat + 96, d_h3b[q], NU*NB);
                cpwait();
                {
                    ull a01[8] = {0,0,0,0,0,0,0,0}, a23[8] = {0,0,0,0,0,0,0,0};
                    int k0 = (403*wib) >> 3, k1 = (403*(wib+1)) >> 3;
                    accT8<403*16>(a01, a23, sb + OFF_PR*4, sb + OFF_CAT*4, k0, k1, b);
                    store_red8(s_red, wib, b, a01, a23);
                }
                __syncthreads();
                {
                    int uu = (cta-100)*8 + wib;
                    float* dp = d_R3pb[p] + uu*128 + b;
                    __stcg(dp+0,  __ldg(b2+uu)      + red_sum(s_red, 1024, wib, 0,  b));
                    __stcg(dp+32, __ldg(b2+NU+uu)   + red_sum(s_red, 1024, wib, 32, b));
                    __stcg(dp+64, __ldg(b2+2*NU+uu) + red_sum(s_red, 1024, wib, 64, b));
                    __stcg(dp+96, __ldg(b2+3*NU+uu) + red_sum(s_red, 1024, wib, 96, b));
                }
                __syncthreads();
                if (tid == 0) st_rel(d_fr + (cta-100)*SLOT, rt1);

                // ---- attention (CTAs 100-103) ----
                if (cta < 104) {
                    if (tid < 50) spin_ge(d_fh1 + tid*SLOT, rt1);
                    __syncthreads();
                    copy4(s_cat, d_h1[p], NU*NB);
                    cpwait();
                    int ab = (cta-100)*8 + wib;
                    float att = 0.f;
                    if (lane < 30) {
                        float acc = __ldg(batt + lane);
#pragma unroll 8
                        for (int k = 0; k < NU; k++)
                            acc = fmaf(s_cat[k*NB + ab], s_watt[k*30 + lane], acc);
                        att = acc;
                    }
                    float ah = __shfl_sync(FULL, att, (lane < 10) ? lane      : 0);
                    float bh = __shfl_sync(FULL, att, (lane < 10) ? lane + 10 : 10);
                    float kh = __shfl_sync(FULL, att, (lane < 10) ? lane + 20 : 20);
                    float alpha = 0.f, beta = 0.f;
                    if (lane < 10) {
                        alpha = expf(ah);
                        beta  = expf(bh);
                        kapreg = kapreg + expf(kh);
                    }
                    float* sw = s_att + wib*76;
                    for (int c = lane; c < NC; c += 32) sw[c] = 0.f;
                    __syncwarp();
                    int lb = __ldg(lens + ab);
#pragma unroll
                    for (int hh = 0; hh < 2; hh++) {
                        int uu = lane + hh*32;
                        float phi = 0.f;
#pragma unroll
                        for (int g = 0; g < NKG; g++) {
                            float ag = __shfl_sync(FULL, alpha,  g);
                            float bg = __shfl_sync(FULL, beta,   g);
                            float kg = __shfl_sync(FULL, kapreg, g);
                            float df = kg - (float)uu;
                            phi = fmaf(ag, expf(-bg*df*df), phi);
                        }
                        if (uu < NUC && uu < lb) {
                            int c = __ldg(chars + ab*NUC + uu);
                            atomicAdd(&sw[c], phi);
                        }
                    }
                    __syncwarp();
                    for (int c = lane; c < NC; c += 32) __stcg(&d_wTb[p][c*NB + ab], sw[c]);
                    __syncthreads();
                    if (tid == 0) st_rel(d_fw + (cta-100)*SLOT, rt1);
                }
            }

            // ================= common S4 (CTAs 50-149) =================
            if (tid < 50) spin_ge(d_fh2 + tid*SLOT, rt1);
            else if (tid >= 50 && tid < 54) spin_ge(d_fw + (tid-50)*SLOT, rt1);
            else if (tid >= 64 && tid < 114) spin_ge(d_fr + (tid-64)*SLOT, rt1);
            __syncthreads();
            copy4(s_cat,        d_wTb[p], NC*NB);
            copy4(s_cat + 2336, d_h2b[p], NU*NB);
            cpwait();
            {
                ull a01[4] = {0,0,0,0}, a23[4] = {0,0,0,0};
                int k0 = (473*wib) >> 3, k1 = (473*(wib+1)) >> 3;
                accT4<473*16>(a01, a23, sb + OFF_P2WH*4, sb + OFF_CAT*4, k0, k1, b);
                store_red4(s_red, wib, b, a01, a23);
            }
            __syncthreads();
            if (wib < 4) {
                int uu = (cta-50)*4 + wib;
                const float* rr = d_R3pb[p] + uu*128 + b;
                float zi = __ldcg(rr)    + red_sum(s_red, 512, wib, 0,  b);
                float zf = __ldcg(rr+32) + red_sum(s_red, 512, wib, 32, b);
                float zg = __ldcg(rr+64) + red_sum(s_red, 512, wib, 64, b);
                float zo = __ldcg(rr+96) + red_sum(s_red, 512, wib, 96, b);
                float ig = sigf(zi + __ldg(p2+uu)      * c3reg);
                float fg = sigf(zf + __ldg(p2+NU+uu)   * c3reg);
                float cn = fg*c3reg + ig*tanhf(zg);
                float og = sigf(zo + __ldg(p2+2*NU+uu) * cn);
                c3reg = cn;
                float hv = og * tanhf(cn);
                __stcg(&d_h3b[p][uu*NB + b], hv);
                __stcg(&d_h3all[(t*NU + uu)*NB + b], hv);
            }
            __syncthreads();
            if (tid == 0) st_rel(d_fh3 + (cta-50)*SLOT, rt1);
        }
    }

    // ================= MDN head =================
    if (tid < 100) spin_ge(d_fh3 + tid*SLOT, (unsigned)NT);
    __syncthreads();

    const int gw = cta*NWARP + wib;
    const int NW = NCTA*NWARP;
    for (int task = gw; task < NB*NT; task += NW) {
        int bb = task / NT;
        int tt = task - bb*NT;
        const float* h3p = d_h3all + (tt*NU)*NB + bb;

        int j0 = lane, j1 = lane + 32, j2 = lane + 64, j3 = lane + 96;
        float a0 = __ldg(bmdn + j0);
        float a1 = __ldg(bmdn + j1);
        float a2 = __ldg(bmdn + j2);
        float a3 = (j3 < NO) ? __ldg(bmdn + j3) : 0.f;
#pragma unroll 4
        for (int k = 0; k < NU; k++) {
            float hv = __ldcg(h3p + k*NB);
            const float* wr = Wmdn + k*NO;
            a0 = fmaf(hv, __ldg(wr + j0), a0);
            a1 = fmaf(hv, __ldg(wr + j1), a1);
            a2 = fmaf(hv, __ldg(wr + j2), a2);
            a3 = fmaf(hv, (j3 < NO) ? __ldg(wr + j3) : 0.f, a3);
        }
        float v = (lane < 20) ? a0 : -INFINITY;
#pragma unroll
        for (int off = 16; off > 0; off >>= 1) v = fmaxf(v, __shfl_xor_sync(FULL, v, off));
        float e = (lane < 20) ? expf(a0 - v) : 0.f;
        float s = e;
#pragma unroll
        for (int off = 16; off > 0; off >>= 1) s += __shfl_xor_sync(FULL, s, off);

        float* op = out + (bb*NT + tt)*NO;
        op[j0] = (lane < 20) ? (e / s) : a0;       // pi | mu1
        op[j1] = (j1 >= 60) ? expf(a1) : a1;       // mu | s1(60-63)
        op[j2] = expf(a2);                         // s1/s2
        if (j3 < NO) {
            float o3;
            if (j3 < 100)      o3 = expf(a3);      // s2
            else if (j3 < 120) o3 = tanhf(a3);     // rho
            else               o3 = sigf(a3);      // eos
            op[j3] = o3;
        }
    }
}

// =====================================================================
// launch
// =====================================================================
extern "C" void kernel_launch(void* const* d_in, const int* in_sizes, int n_in,
                              void* d_out, int out_size)
{
    const float* strokes = (const float*)d_in[0];
    const int*   chars   = (const int*)  d_in[1];
    const int*   lens    = (const int*)  d_in[2];
    const float* Wx0 = (const float*)d_in[3];
    const float* Wh0 = (const float*)d_in[4];
    const float* b0  = (const float*)d_in[5];
    const float* p0  = (const float*)d_in[6];
    const float* Wx1 = (const float*)d_in[7];
    const float* Wh1 = (const float*)d_in[8];
    const float* b1  = (const float*)d_in[9];
    const float* p1  = (const float*)d_in[10];
    const float* Wx2 = (const float*)d_in[11];
    const float* Wh2 = (const float*)d_in[12];
    const float* b2  = (const float*)d_in[13];
    const float* p2  = (const float*)d_in[14];
    const float* Watt = (const float*)d_in[15];
    const float* batt = (const float*)d_in[16];
    const float* Wmdn = (const float*)d_in[17];
    const float* bmdn = (const float*)d_in[18];
    float* out = (float*)d_out;

    static int smem_set = 0;
    if (!smem_set) {
        cudaFuncSetAttribute(rnn_kernel, cudaFuncAttributeMaxDynamicSharedMemorySize, SMEM_BYTES);
        smem_set = 1;
    }

    pack_kernel<<<256, 256>>>(Wx0, Wh0, Wx1, Wh1, Wx2, Wh2);
    rnn_kernel<<<NCTA, NTH, SMEM_BYTES>>>(strokes, chars, lens,
                                          b0, p0, b1, p1, b2, p2,
                                          Watt, batt, Wmdn, bmdn, out);
}

// round 16
// speedup vs baseline: 1.0155x; 1.0155x over previous
#include <cuda_runtime.h>
#include <math.h>

#define NB 32      // batch
#define NT 400     // timesteps
#define NU 400     // LSTM units
#define NKG 10     // attention gaussians
#define NC 73      // alphabet
#define NUC 50     // char positions
#define NO 121     // MDN outputs
#define H4 1600    // 4*NU
#define NCTA 150
#define NTH 256
#define NWARP 8
#define SLOT 32

// smem layout (float offsets) — identical to R14
#define OFF_CAT  0        // 15232: staged concatenated state [k][b]
#define OFF_RED  15232    // 8192: K-split partial reduction
#define OFF_ATT  23424    // 608: attention scatter scratch
#define OFF_P0   24032    // A: 476*8 float4 = 15232 floats
#define OFF_P1H  39264    // A: 400*8 float4 = 12800
#define OFF_P1W  52064    // A: 73*8 float4 = 2336   (A end 54400)
#define OFF_PR   24032    // B/C: 403*8 float4 = 12896
#define OFF_P2WH 36928    // S4: 473*4 float4 = 7568
#define OFF_WATT 44496    // C att: 400*30 = 12000 (end 56496)
#define SMEM_FLOATS 56496
#define SMEM_BYTES (SMEM_FLOATS*4)   // 225984

typedef unsigned long long ull;

// ---------------- k-major packed weights: [slice][k][unit-in-slice] float4 ----------------
__device__ float4 d_Q0  [50*476*8];   // A slices
__device__ float4 d_Q1h [50*400*8];
__device__ float4 d_Q1w [50*73*8];
__device__ float4 d_Q1r [50*403*8];   // B slices
__device__ float4 d_Q2r [50*403*8];   // C slices
__device__ float4 d_Q2wh[100*473*4];  // S4 slices (4 units each)

// ---------------- double-buffered state [parity][u*NB+b] ----------------
__device__ float d_h1 [2][NU*NB];
__device__ float d_h2b[2][NU*NB];
__device__ float d_h3b[2][NU*NB];
__device__ float d_wTb[2][NC*NB];
__device__ float d_Z2pb[2][NU*4*NB];
__device__ float d_R3pb[2][NU*4*NB];
__device__ float d_h3all[NT*NU*NB];

// ---------------- versioned flags (padded) ----------------
__device__ unsigned d_fh1[50*SLOT];
__device__ unsigned d_fw [4*SLOT];
__device__ unsigned d_fh2[50*SLOT];
__device__ unsigned d_fz [50*SLOT];
__device__ unsigned d_fr [50*SLOT];
__device__ unsigned d_fh3[100*SLOT];

// =====================================================================
// pack kernel — k-major gate-interleaved slices
// =====================================================================
__global__ void pack_kernel(const float* __restrict__ Wx0, const float* __restrict__ Wh0,
                            const float* __restrict__ Wx1, const float* __restrict__ Wh1,
                            const float* __restrict__ Wx2, const float* __restrict__ Wh2)
{
    int idx = blockIdx.x * blockDim.x + threadIdx.x;
    int str = gridDim.x * blockDim.x;

    for (int e = idx; e < 50*SLOT; e += str) {
        d_fh1[e]=0u; d_fh2[e]=0u; d_fz[e]=0u; d_fr[e]=0u;
    }
    for (int e = idx; e < 100*SLOT; e += str) d_fh3[e] = 0u;
    for (int e = idx; e < 4*SLOT; e += str) d_fw[e] = 0u;
    for (int e = idx; e < NU*NB; e += str) {
        d_h1[0][e]=0.f; d_h1[1][e]=0.f; d_h2b[0][e]=0.f; d_h2b[1][e]=0.f;
        d_h3b[0][e]=0.f; d_h3b[1][e]=0.f;
    }
    for (int e = idx; e < NC*NB; e += str) { d_wTb[0][e]=0.f; d_wTb[1][e]=0.f; }

    // d_Q0: [cta][k][ul], u = cta*8+ul; k<76 -> Wx0 row k, else Wh0 row k-76
    for (int e = idx; e < 50*476*8; e += str) {
        int cta = e / (476*8), rem = e - cta*(476*8);
        int k = rem >> 3, ul = rem & 7;
        int u = cta*8 + ul;
        const float* s = (k < 76) ? (Wx0 + k*H4) : (Wh0 + (k-76)*H4);
        d_Q0[e] = make_float4(s[u], s[NU+u], s[2*NU+u], s[3*NU+u]);
    }
    // d_Q1h: Wx1 rows 76..475
    for (int e = idx; e < 50*400*8; e += str) {
        int cta = e / (400*8), rem = e - cta*(400*8);
        int k = rem >> 3, ul = rem & 7;
        int u = cta*8 + ul;
        const float* s = Wx1 + (76+k)*H4;
        d_Q1h[e] = make_float4(s[u], s[NU+u], s[2*NU+u], s[3*NU+u]);
    }
    // d_Q1w: Wx1 rows 3..75
    for (int e = idx; e < 50*73*8; e += str) {
        int cta = e / (73*8), rem = e - cta*(73*8);
        int k = rem >> 3, ul = rem & 7;
        int u = cta*8 + ul;
        const float* s = Wx1 + (3+k)*H4;
        d_Q1w[e] = make_float4(s[u], s[NU+u], s[2*NU+u], s[3*NU+u]);
    }
    // d_Q1r: k<3 -> Wx1 row k, else Wh1 row k-3
    for (int e = idx; e < 50*403*8; e += str) {
        int cta = e / (403*8), rem = e - cta*(403*8);
        int k = rem >> 3, ul = rem & 7;
        int u = cta*8 + ul;
        const float* s = (k < 3) ? (Wx1 + k*H4) : (Wh1 + (k-3)*H4);
        d_Q1r[e] = make_float4(s[u], s[NU+u], s[2*NU+u], s[3*NU+u]);
    }
    // d_Q2r: k<3 -> Wx2 row k, else Wh2 row k-3
    for (int e = idx; e < 50*403*8; e += str) {
        int cta = e / (403*8), rem = e - cta*(403*8);
        int k = rem >> 3, ul = rem & 7;
        int u = cta*8 + ul;
        const float* s = (k < 3) ? (Wx2 + k*H4) : (Wh2 + (k-3)*H4);
        d_Q2r[e] = make_float4(s[u], s[NU+u], s[2*NU+u], s[3*NU+u]);
    }
    // d_Q2wh: [scta][k][ul], u = scta*4+ul; Wx2 rows 3..475
    for (int e = idx; e < 100*473*4; e += str) {
        int scta = e / (473*4), rem = e - scta*(473*4);
        int k = rem >> 2, ul = rem & 3;
        int u = scta*4 + ul;
        const float* s = Wx2 + (3+k)*H4;
        d_Q2wh[e] = make_float4(s[u], s[NU+u], s[2*NU+u], s[3*NU+u]);
    }
}

// =====================================================================
// helpers
// =====================================================================
__device__ __forceinline__ float sigf(float x) { return 1.f / (1.f + expf(-x)); }

__device__ __forceinline__ ull pk2(float v) {
    ull r; asm("mov.b64 %0, {%1, %1};" : "=l"(r) : "f"(v)); return r;
}
__device__ __forceinline__ void upk(ull v, float& lo, float& hi) {
    asm("mov.b64 {%0, %1}, %2;" : "=f"(lo), "=f"(hi) : "l"(v));
}
__device__ __forceinline__ void fma2(ull& d, ull a, ull b) {
    asm("fma.rn.f32x2 %0, %1, %2, %0;" : "+l"(d) : "l"(a), "l"(b));
}

__device__ __forceinline__ void st_rel(unsigned* p, unsigned v) {
    asm volatile("{ .reg .u64 a; cvta.to.global.u64 a, %0; st.release.gpu.global.u32 [a], %1; }"
                 :: "l"(p), "r"(v) : "memory");
}
__device__ __forceinline__ unsigned ld_rlx(const unsigned* p) {
    unsigned v;
    asm volatile("{ .reg .u64 a; cvta.to.global.u64 a, %1; ld.relaxed.gpu.global.u32 %0, [a]; }"
                 : "=r"(v) : "l"(p) : "memory");
    return v;
}
__device__ __forceinline__ void spin_ge(const unsigned* p, unsigned r) {
    while (ld_rlx(p) < r) { }
}

// staging copy: cp.async.cg — L1 bypass global->shared
__device__ __forceinline__ void copy4(float* dst, const float* src, int nfl)
{
    unsigned base = (unsigned)__cvta_generic_to_shared(dst);
    int n4 = nfl >> 2;
    for (int i = threadIdx.x; i < n4; i += NTH) {
        asm volatile("cp.async.cg.shared.global [%0], [%1], 16;"
                     :: "r"(base + i*16), "l"((const char*)src + i*16) : "memory");
    }
}
__device__ __forceinline__ void cpwait()
{
    asm volatile("cp.async.commit_group;" ::: "memory");
    asm volatile("cp.async.wait_group 0;" ::: "memory");
    __syncthreads();
}

// K-transposed accumulate, k-major weights: per k one 128B block, unit offsets
// are true LDS immediates (0..112). 2 address adds per k total.
__device__ __forceinline__ void accT8(ull a01[8], ull a23[8],
                                      unsigned wbyte, unsigned vbyte, int k0, int k1, int b)
{
    unsigned va = vbyte + b*4 + k0*(NB*4);
    unsigned wa = wbyte + k0*128;
#pragma unroll 2
    for (int k = k0; k < k1; k++) {
        float hv;
        asm("ld.shared.b32 %0, [%1];" : "=f"(hv) : "r"(va));
        ull hh = pk2(hv);
#pragma unroll
        for (int u = 0; u < 8; u++) {
            ull wx, wy;
            asm("ld.shared.v2.b64 {%0,%1}, [%2];" : "=l"(wx), "=l"(wy) : "r"(wa + u*16));
            fma2(a01[u], wx, hh);
            fma2(a23[u], wy, hh);
        }
        va += NB*4; wa += 128;
    }
}

__device__ __forceinline__ void accT4(ull a01[4], ull a23[4],
                                      unsigned wbyte, unsigned vbyte, int k0, int k1, int b)
{
    unsigned va = vbyte + b*4 + k0*(NB*4);
    unsigned wa = wbyte + k0*64;
#pragma unroll 2
    for (int k = k0; k < k1; k++) {
        float hv;
        asm("ld.shared.b32 %0, [%1];" : "=f"(hv) : "r"(va));
        ull hh = pk2(hv);
#pragma unroll
        for (int u = 0; u < 4; u++) {
            ull wx, wy;
            asm("ld.shared.v2.b64 {%0,%1}, [%2];" : "=l"(wx), "=l"(wy) : "r"(wa + u*16));
            fma2(a01[u], wx, hh);
            fma2(a23[u], wy, hh);
        }
        va += NB*4; wa += 64;
    }
}

__device__ __forceinline__ void store_red8(float* s_red, int wib, int b,
                                           const ull a01[8], const ull a23[8])
{
    float* rp = s_red + wib*1024 + b;
#pragma unroll
    for (int u = 0; u < 8; u++) {
        float gi,gf,gg,go;
        upk(a01[u], gi, gf); upk(a23[u], gg, go);
        rp[u*128+0]=gi; rp[u*128+32]=gf; rp[u*128+64]=gg; rp[u*128+96]=go;
    }
}
__device__ __forceinline__ void store_red4(float* s_red, int wib, int b,
                                           const ull a01[4], const ull a23[4])
{
    float* rp = s_red + wib*512 + b;
#pragma unroll
    for (int u = 0; u < 4; u++) {
        float gi,gf,gg,go;
        upk(a01[u], gi, gf); upk(a23[u], gg, go);
        rp[u*128+0]=gi; rp[u*128+32]=gf; rp[u*128+64]=gg; rp[u*128+96]=go;
    }
}

__device__ __forceinline__ float red_sum(const float* s_red, int wstr, int us, int goff, int b)
{
    float s = 0.f;
#pragma unroll
    for (int w = 0; w < 8; w++) s += s_red[w*wstr + us*128 + goff + b];
    return s;
}

// =====================================================================
// persistent RNN kernel — R14 dataflow + k-major weights
// =====================================================================
__global__ void __launch_bounds__(NTH, 1)
rnn_kernel(const float* __restrict__ strokes,
           const int*   __restrict__ chars,
           const int*   __restrict__ lens,
           const float* __restrict__ b0, const float* __restrict__ p0,
           const float* __restrict__ b1, const float* __restrict__ p1,
           const float* __restrict__ b2, const float* __restrict__ p2,
           const float* __restrict__ Watt, const float* __restrict__ batt,
           const float* __restrict__ Wmdn, const float* __restrict__ bmdn,
           float* __restrict__ out)
{
    extern __shared__ float smem[];
    float* s_cat  = smem + OFF_CAT;
    float* s_red  = smem + OFF_RED;
    float* s_att  = smem + OFF_ATT;
    float* s_watt = smem + OFF_WATT;
    const unsigned sb = (unsigned)__cvta_generic_to_shared(smem);

    const int cta  = blockIdx.x;
    const int tid  = threadIdx.x;
    const int lane = tid & 31;
    const int wib  = tid >> 5;
    const int b    = lane;
    const unsigned FULL = 0xffffffffu;

    // ---- preload weight slices ----
    if (cta < 50) {
        copy4(smem + OFF_P0,  (const float*)(d_Q0  + cta*476*8), 476*8*4);
        copy4(smem + OFF_P1H, (const float*)(d_Q1h + cta*400*8), 400*8*4);
        copy4(smem + OFF_P1W, (const float*)(d_Q1w + cta*73*8),  73*8*4);
    } else {
        const float4* prsrc = (cta < 100) ? (d_Q1r + (cta-50)*403*8)
                                          : (d_Q2r + (cta-100)*403*8);
        copy4(smem + OFF_PR,   (const float*)prsrc, 403*8*4);
        copy4(smem + OFF_P2WH, (const float*)(d_Q2wh + (cta-50)*473*4), 473*4*4);
        if (cta >= 100 && cta < 104) copy4(s_watt, Watt, NU*30);
    }
    cpwait();

    float c1reg = 0.f, c2reg = 0.f;  // A: unit = cta*8+wib
    float c3reg = 0.f;               // S4 CTAs (>=50), wib<4: unit = (cta-50)*4+wib
    float kapreg = 0.f;              // att CTAs 100-103

    for (int t = 0; t < NT; t++) {
        const int p = t & 1, q = p ^ 1;
        const unsigned rt = (unsigned)t, rt1 = (unsigned)(t+1);

        if (cta < 50) {
            // ================= A: S1 =================
            if (tid < 50) spin_ge(d_fh1 + tid*SLOT, rt);
            else if (tid < 54) spin_ge(d_fw + (tid-50)*SLOT, rt);
            __syncthreads();
            if (tid < 96) s_cat[tid] = __ldg(strokes + ((tid & 31)*NT + t)*3 + (tid >> 5));
            copy4(s_cat + 96,   d_wTb[q], NC*NB);
            copy4(s_cat + 2432, d_h1[q],  NU*NB);
            cpwait();
            {
                ull a01[8] = {0,0,0,0,0,0,0,0}, a23[8] = {0,0,0,0,0,0,0,0};
                int k0 = (476*wib) >> 3, k1 = (476*(wib+1)) >> 3;
                accT8(a01, a23, sb + OFF_P0*4, sb + OFF_CAT*4, k0, k1, b);
                store_red8(s_red, wib, b, a01, a23);
            }
            __syncthreads();
            {
                int uu = cta*8 + wib;
                float zi = __ldg(b0+uu)      + red_sum(s_red, 1024, wib, 0,  b);
                float zf = __ldg(b0+NU+uu)   + red_sum(s_red, 1024, wib, 32, b);
                float zg = __ldg(b0+2*NU+uu) + red_sum(s_red, 1024, wib, 64, b);
                float zo = __ldg(b0+3*NU+uu) + red_sum(s_red, 1024, wib, 96, b);
                float ig = sigf(zi + __ldg(p0+uu)      * c1reg);
                float fg = sigf(zf + __ldg(p0+NU+uu)   * c1reg);
                float cn = fg*c1reg + ig*tanhf(zg);
                float og = sigf(zo + __ldg(p0+2*NU+uu) * cn);
                c1reg = cn;
                __stcg(&d_h1[p][uu*NB + b], og * tanhf(cn));
            }
            __syncthreads();
            if (tid == 0) st_rel(d_fh1 + cta*SLOT, rt1);

            // ================= A: S2/3 =================
            if (tid < 50) spin_ge(d_fh1 + tid*SLOT, rt1);
            __syncthreads();
            copy4(s_cat, d_h1[p], NU*NB);   // h1[t] at cat[0:12800]
            cpwait();
            {
                ull a01[8] = {0,0,0,0,0,0,0,0}, a23[8] = {0,0,0,0,0,0,0,0};
                int k0 = wib*50, k1 = k0 + 50;
                accT8(a01, a23, sb + OFF_P1H*4, sb + OFF_CAT*4, k0, k1, b);
                if (tid < 4) spin_ge(d_fw + tid*SLOT, rt1);
                if (tid == 4) spin_ge(d_fz + cta*SLOT, rt1);
                __syncthreads();
                copy4(s_cat + 12800, d_wTb[p], NC*NB);   // w[t] at cat[12800:15136]
                cpwait();
                int kw0 = (73*wib) >> 3, kw1 = (73*(wib+1)) >> 3;
                accT8(a01, a23, sb + OFF_P1W*4, sb + (OFF_CAT+12800)*4, kw0, kw1, b);
                store_red8(s_red, wib, b, a01, a23);
            }
            __syncthreads();
            {
                int uu = cta*8 + wib;
                const float* zp = d_Z2pb[p] + uu*128 + b;
                float zi = __ldcg(zp)    + red_sum(s_red, 1024, wib, 0,  b);
                float zf = __ldcg(zp+32) + red_sum(s_red, 1024, wib, 32, b);
                float zg = __ldcg(zp+64) + red_sum(s_red, 1024, wib, 64, b);
                float zo = __ldcg(zp+96) + red_sum(s_red, 1024, wib, 96, b);
                float ig = sigf(zi + __ldg(p1+uu)      * c2reg);
                float fg = sigf(zf + __ldg(p1+NU+uu)   * c2reg);
                float cn = fg*c2reg + ig*tanhf(zg);
                float og = sigf(zo + __ldg(p1+2*NU+uu) * cn);
                c2reg = cn;
                __stcg(&d_h2b[p][uu*NB + b], og * tanhf(cn));
            }
            __syncthreads();
            if (tid == 0) st_rel(d_fh2 + cta*SLOT, rt1);
        } else {
            if (cta < 100) {
                // ================= B: R2 =================
                if (tid < 50) spin_ge(d_fh2 + tid*SLOT, rt);
                __syncthreads();
                if (tid < 96) s_cat[tid] = __ldg(strokes + ((tid & 31)*NT + t)*3 + (tid >> 5));
                copy4(s_cat + 96, d_h2b[q], NU*NB);
                cpwait();
                {
                    ull a01[8] = {0,0,0,0,0,0,0,0}, a23[8] = {0,0,0,0,0,0,0,0};
                    int k0 = (403*wib) >> 3, k1 = (403*(wib+1)) >> 3;
                    accT8(a01, a23, sb + OFF_PR*4, sb + OFF_CAT*4, k0, k1, b);
                    store_red8(s_red, wib, b, a01, a23);
                }
                __syncthreads();
                {
                    int uu = (cta-50)*8 + wib;
                    float* dp = d_Z2pb[p] + uu*128 + b;
                    __stcg(dp+0,  __ldg(b1+uu)      + red_sum(s_red, 1024, wib, 0,  b));
                    __stcg(dp+32, __ldg(b1+NU+uu)   + red_sum(s_red, 1024, wib, 32, b));
                    __stcg(dp+64, __ldg(b1+2*NU+uu) + red_sum(s_red, 1024, wib, 64, b));
                    __stcg(dp+96, __ldg(b1+3*NU+uu) + red_sum(s_red, 1024, wib, 96, b));
                }
                __syncthreads();
                if (tid == 0) st_rel(d_fz + (cta-50)*SLOT, rt1);
            } else {
                // ================= C: R3 =================
                if (tid < 100) spin_ge(d_fh3 + tid*SLOT, rt);
                __syncthreads();
                if (tid < 96) s_cat[tid] = __ldg(strokes + ((tid & 31)*NT + t)*3 + (tid >> 5));
                copy4(s_cat + 96, d_h3b[q], NU*NB);
                cpwait();
                {
                    ull a01[8] = {0,0,0,0,0,0,0,0}, a23[8] = {0,0,0,0,0,0,0,0};
                    int k0 = (403*wib) >> 3, k1 = (403*(wib+1)) >> 3;
                    accT8(a01, a23, sb + OFF_PR*4, sb + OFF_CAT*4, k0, k1, b);
                    store_red8(s_red, wib, b, a01, a23);
                }
                __syncthreads();
                {
                    int uu = (cta-100)*8 + wib;
                    float* dp = d_R3pb[p] + uu*128 + b;
                    __stcg(dp+0,  __ldg(b2+uu)      + red_sum(s_red, 1024, wib, 0,  b));
                    __stcg(dp+32, __ldg(b2+NU+uu)   + red_sum(s_red, 1024, wib, 32, b));
                    __stcg(dp+64, __ldg(b2+2*NU+uu) + red_sum(s_red, 1024, wib, 64, b));
                    __stcg(dp+96, __ldg(b2+3*NU+uu) + red_sum(s_red, 1024, wib, 96, b));
                }
                __syncthreads();
                if (tid == 0) st_rel(d_fr + (cta-100)*SLOT, rt1);

                // ---- attention (CTAs 100-103) ----
                if (cta < 104) {
                    if (tid < 50) spin_ge(d_fh1 + tid*SLOT, rt1);
                    __syncthreads();
                    copy4(s_cat, d_h1[p], NU*NB);
                    cpwait();
                    int ab = (cta-100)*8 + wib;
                    float att = 0.f;
                    if (lane < 30) {
                        float acc = __ldg(batt + lane);
#pragma unroll 8
                        for (int k = 0; k < NU; k++)
                            acc = fmaf(s_cat[k*NB + ab], s_watt[k*30 + lane], acc);
                        att = acc;
                    }
                    float ah = __shfl_sync(FULL, att, (lane < 10) ? lane      : 0);
                    float bh = __shfl_sync(FULL, att, (lane < 10) ? lane + 10 : 10);
                    float kh = __shfl_sync(FULL, att, (lane < 10) ? lane + 20 : 20);
                    float alpha = 0.f, beta = 0.f;
                    if (lane < 10) {
                        alpha = expf(ah);
                        beta  = expf(bh);
                        kapreg = kapreg + expf(kh);
                    }
                    float* sw = s_att + wib*76;
                    for (int c = lane; c < NC; c += 32) sw[c] = 0.f;
                    __syncwarp();
                    int lb = __ldg(lens + ab);
#pragma unroll
                    for (int hh = 0; hh < 2; hh++) {
                        int uu = lane + hh*32;
                        float phi = 0.f;
#pragma unroll
                        for (int g = 0; g < NKG; g++) {
                            float ag = __shfl_sync(FULL, alpha,  g);
                            float bg = __shfl_sync(FULL, beta,   g);
                            float kg = __shfl_sync(FULL, kapreg, g);
                            float df = kg - (float)uu;
                            phi = fmaf(ag, expf(-bg*df*df), phi);
                        }
                        if (uu < NUC && uu < lb) {
                            int c = __ldg(chars + ab*NUC + uu);
                            atomicAdd(&sw[c], phi);
                        }
                    }
                    __syncwarp();
                    for (int c = lane; c < NC; c += 32) __stcg(&d_wTb[p][c*NB + ab], sw[c]);
                    __syncthreads();
                    if (tid == 0) st_rel(d_fw + (cta-100)*SLOT, rt1);
                }
            }

            // ================= common S4 (CTAs 50-149) =================
            if (tid < 50) spin_ge(d_fh2 + tid*SLOT, rt1);
            else if (tid < 54) spin_ge(d_fw + (tid-50)*SLOT, rt1);
            else if (tid == 54) spin_ge(d_fr + ((cta-50)>>1)*SLOT, rt1);
            __syncthreads();
            copy4(s_cat,        d_wTb[p], NC*NB);
            copy4(s_cat + 2336, d_h2b[p], NU*NB);
            cpwait();
            {
                ull a01[4] = {0,0,0,0}, a23[4] = {0,0,0,0};
                int k0 = (473*wib) >> 3, k1 = (473*(wib+1)) >> 3;
                accT4(a01, a23, sb + OFF_P2WH*4, sb + OFF_CAT*4, k0, k1, b);
                store_red4(s_red, wib, b, a01, a23);
            }
            __syncthreads();
            if (wib < 4) {
                int uu = (cta-50)*4 + wib;
                const float* rr = d_R3pb[p] + uu*128 + b;
                float zi = __ldcg(rr)    + red_sum(s_red, 512, wib, 0,  b);
                float zf = __ldcg(rr+32) + red_sum(s_red, 512, wib, 32, b);
                float zg = __ldcg(rr+64) + red_sum(s_red, 512, wib, 64, b);
                float zo = __ldcg(rr+96) + red_sum(s_red, 512, wib, 96, b);
                float ig = sigf(zi + __ldg(p2+uu)      * c3reg);
                float fg = sigf(zf + __ldg(p2+NU+uu)   * c3reg);
                float cn = fg*c3reg + ig*tanhf(zg);
                float og = sigf(zo + __ldg(p2+2*NU+uu) * cn);
                c3reg = cn;
                float hv = og * tanhf(cn);
                __stcg(&d_h3b[p][uu*NB + b], hv);
                __stcg(&d_h3all[(t*NU + uu)*NB + b], hv);
            }
            __syncthreads();
            if (tid == 0) st_rel(d_fh3 + (cta-50)*SLOT, rt1);
        }
    }

    // ================= MDN head =================
    if (tid < 100) spin_ge(d_fh3 + tid*SLOT, (unsigned)NT);
    __syncthreads();

    const int gw = cta*NWARP + wib;
    const int NW = NCTA*NWARP;
    for (int task = gw; task < NB*NT; task += NW) {
        int bb = task / NT;
        int tt = task - bb*NT;
        const float* h3p = d_h3all + (tt*NU)*NB + bb;

        int j0 = lane, j1 = lane + 32, j2 = lane + 64, j3 = lane + 96;
        float a0 = __ldg(bmdn + j0);
        float a1 = __ldg(bmdn + j1);
        float a2 = __ldg(bmdn + j2);
        float a3 = (j3 < NO) ? __ldg(bmdn + j3) : 0.f;
#pragma unroll 4
        for (int k = 0; k < NU; k++) {
            float hv = __ldcg(h3p + k*NB);
            const float* wr = Wmdn + k*NO;
            a0 = fmaf(hv, __ldg(wr + j0), a0);
            a1 = fmaf(hv, __ldg(wr + j1), a1);
            a2 = fmaf(hv, __ldg(wr + j2), a2);
            a3 = fmaf(hv, (j3 < NO) ? __ldg(wr + j3) : 0.f, a3);
        }
        float v = (lane < 20) ? a0 : -INFINITY;
#pragma unroll
        for (int off = 16; off > 0; off >>= 1) v = fmaxf(v, __shfl_xor_sync(FULL, v, off));
        float e = (lane < 20) ? expf(a0 - v) : 0.f;
        float s = e;
#pragma unroll
        for (int off = 16; off > 0; off >>= 1) s += __shfl_xor_sync(FULL, s, off);

        float* op = out + (bb*NT + tt)*NO;
        op[j0] = (lane < 20) ? (e / s) : a0;       // pi | mu1
        op[j1] = (j1 >= 60) ? expf(a1) : a1;       // mu | s1(60-63)
        op[j2] = expf(a2);                         // s1/s2
        if (j3 < NO) {
            float o3;
            if (j3 < 100)      o3 = expf(a3);      // s2
            else if (j3 < 120) o3 = tanhf(a3);     // rho
            else               o3 = sigf(a3);      // eos
            op[j3] = o3;
        }
    }
}

// =====================================================================
// launch
// =====================================================================
extern "C" void kernel_launch(void* const* d_in, const int* in_sizes, int n_in,
                              void* d_out, int out_size)
{
    const float* strokes = (const float*)d_in[0];
    const int*   chars   = (const int*)  d_in[1];
    const int*   lens    = (const int*)  d_in[2];
    const float* Wx0 = (const float*)d_in[3];
    const float* Wh0 = (const float*)d_in[4];
    const float* b0  = (const float*)d_in[5];
    const float* p0  = (const float*)d_in[6];
    const float* Wx1 = (const float*)d_in[7];
    const float* Wh1 = (const float*)d_in[8];
    const float* b1  = (const float*)d_in[9];
    const float* p1  = (const float*)d_in[10];
    const float* Wx2 = (const float*)d_in[11];
    const float* Wh2 = (const float*)d_in[12];
    const float* b2  = (const float*)d_in[13];
    const float* p2  = (const float*)d_in[14];
    const float* Watt = (const float*)d_in[15];
    const float* batt = (const float*)d_in[16];
    const float* Wmdn = (const float*)d_in[17];
    const float* bmdn = (const float*)d_in[18];
    float* out = (float*)d_out;

    static int smem_set = 0;
    if (!smem_set) {
        cudaFuncSetAttribute(rnn_kernel, cudaFuncAttributeMaxDynamicSharedMemorySize, SMEM_BYTES);
        smem_set = 1;
    }

    pack_kernel<<<256, 256>>>(Wx0, Wh0, Wx1, Wh1, Wx2, Wh2);
    rnn_kernel<<<NCTA, NTH, SMEM_BYTES>>>(strokes, chars, lens,
                                          b0, p0, b1, p1, b2, p2,
                                          Watt, batt, Wmdn, bmdn, out);
}

// round 17
// speedup vs baseline: 1.2694x; 1.2501x over previous
#include <cuda_runtime.h>
#include <math.h>

#define NB 32      // batch
#define NT 400     // timesteps
#define NU 400     // LSTM units
#define NKG 10     // attention gaussians
#define NC 73      // alphabet
#define NUC 50     // char positions
#define NO 121     // MDN outputs
#define H4 1600    // 4*NU
#define NCTA 150
#define NTH 256
#define NWARP 8
#define SLOT 32

// smem layout (float offsets)
#define OFF_CAT  0        // 15232: staged concatenated state [k][b]
#define OFF_RED  15232    // 8192: K-split partial reduction / att partials
#define OFF_ATT  23424    // 608: attention scatter scratch
#define OFF_P0   24032    // A: 476*8 float4 = 15232 floats
#define OFF_P1H  39264    // A: 400*8 float4 = 12800
#define OFF_P1W  52064    // A: 73*8 float4 = 2336   (A end 54400)
#define OFF_WAU  54400    // A: Watt slice 8*30 = 240 (end 54640)
#define OFF_PR   24032    // B/C: 403*8 float4 = 12896
#define OFF_P2WH 36928    // S4: 473*4 float4 = 7568
#define OFF_KAP  44496    // finalizer CTAs: kappa state 80 floats
#define SMEM_FLOATS 56496
#define SMEM_BYTES (SMEM_FLOATS*4)   // 225984

typedef unsigned long long ull;

// ---------------- k-major packed weights: [slice][k][unit-in-slice] float4 ----------------
__device__ float4 d_Q0  [50*476*8];   // A slices
__device__ float4 d_Q1h [50*400*8];
__device__ float4 d_Q1w [50*73*8];
__device__ float4 d_Q1r [50*403*8];   // B slices
__device__ float4 d_Q2r [50*403*8];   // C slices
__device__ float4 d_Q2wh[100*473*4];  // S4 slices (4 units each)

// ---------------- double-buffered state [parity][u*NB+b] ----------------
__device__ float d_h1 [2][NU*NB];
__device__ float d_h2b[2][NU*NB];
__device__ float d_h3b[2][NU*NB];
__device__ float d_wTb[2][NC*NB];
__device__ float d_Z2pb[2][NU*4*NB];
__device__ float d_R3pb[2][NU*4*NB];
__device__ float d_h3all[NT*NU*NB];

// ---------------- distributed attention state ----------------
__device__ float    d_attacc[2][30*NB];   // [parity][j*NB+b] partial att sums
__device__ unsigned d_acnt[2*SLOT];       // arrival counters (monotone, +50/use)
__device__ unsigned d_aclean[8*SLOT];     // [parity*4+fc]: clean count

// ---------------- versioned flags (padded) ----------------
__device__ unsigned d_fh1[50*SLOT];
__device__ unsigned d_fw [4*SLOT];
__device__ unsigned d_fh2[50*SLOT];
__device__ unsigned d_fz [50*SLOT];
__device__ unsigned d_fr [50*SLOT];
__device__ unsigned d_fh3[100*SLOT];

// =====================================================================
// pack kernel — k-major gate-interleaved slices
// =====================================================================
__global__ void pack_kernel(const float* __restrict__ Wx0, const float* __restrict__ Wh0,
                            const float* __restrict__ Wx1, const float* __restrict__ Wh1,
                            const float* __restrict__ Wx2, const float* __restrict__ Wh2)
{
    int idx = blockIdx.x * blockDim.x + threadIdx.x;
    int str = gridDim.x * blockDim.x;

    for (int e = idx; e < 50*SLOT; e += str) {
        d_fh1[e]=0u; d_fh2[e]=0u; d_fz[e]=0u; d_fr[e]=0u;
    }
    for (int e = idx; e < 100*SLOT; e += str) d_fh3[e] = 0u;
    for (int e = idx; e < 4*SLOT; e += str) d_fw[e] = 0u;
    for (int e = idx; e < 2*SLOT; e += str) d_acnt[e] = 0u;
    for (int e = idx; e < 8*SLOT; e += str) d_aclean[e] = 1u;
    for (int e = idx; e < 2*30*NB; e += str) d_attacc[e/(30*NB)][e%(30*NB)] = 0.f;
    for (int e = idx; e < NU*NB; e += str) {
        d_h1[0][e]=0.f; d_h1[1][e]=0.f; d_h2b[0][e]=0.f; d_h2b[1][e]=0.f;
        d_h3b[0][e]=0.f; d_h3b[1][e]=0.f;
    }
    for (int e = idx; e < NC*NB; e += str) { d_wTb[0][e]=0.f; d_wTb[1][e]=0.f; }

    for (int e = idx; e < 50*476*8; e += str) {
        int cta = e / (476*8), rem = e - cta*(476*8);
        int k = rem >> 3, ul = rem & 7;
        int u = cta*8 + ul;
        const float* s = (k < 76) ? (Wx0 + k*H4) : (Wh0 + (k-76)*H4);
        d_Q0[e] = make_float4(s[u], s[NU+u], s[2*NU+u], s[3*NU+u]);
    }
    for (int e = idx; e < 50*400*8; e += str) {
        int cta = e / (400*8), rem = e - cta*(400*8);
        int k = rem >> 3, ul = rem & 7;
        int u = cta*8 + ul;
        const float* s = Wx1 + (76+k)*H4;
        d_Q1h[e] = make_float4(s[u], s[NU+u], s[2*NU+u], s[3*NU+u]);
    }
    for (int e = idx; e < 50*73*8; e += str) {
        int cta = e / (73*8), rem = e - cta*(73*8);
        int k = rem >> 3, ul = rem & 7;
        int u = cta*8 + ul;
        const float* s = Wx1 + (3+k)*H4;
        d_Q1w[e] = make_float4(s[u], s[NU+u], s[2*NU+u], s[3*NU+u]);
    }
    for (int e = idx; e < 50*403*8; e += str) {
        int cta = e / (403*8), rem = e - cta*(403*8);
        int k = rem >> 3, ul = rem & 7;
        int u = cta*8 + ul;
        const float* s = (k < 3) ? (Wx1 + k*H4) : (Wh1 + (k-3)*H4);
        d_Q1r[e] = make_float4(s[u], s[NU+u], s[2*NU+u], s[3*NU+u]);
    }
    for (int e = idx; e < 50*403*8; e += str) {
        int cta = e / (403*8), rem = e - cta*(403*8);
        int k = rem >> 3, ul = rem & 7;
        int u = cta*8 + ul;
        const float* s = (k < 3) ? (Wx2 + k*H4) : (Wh2 + (k-3)*H4);
        d_Q2r[e] = make_float4(s[u], s[NU+u], s[2*NU+u], s[3*NU+u]);
    }
    for (int e = idx; e < 100*473*4; e += str) {
        int scta = e / (473*4), rem = e - scta*(473*4);
        int k = rem >> 2, ul = rem & 3;
        int u = scta*4 + ul;
        const float* s = Wx2 + (3+k)*H4;
        d_Q2wh[e] = make_float4(s[u], s[NU+u], s[2*NU+u], s[3*NU+u]);
    }
}

// =====================================================================
// helpers
// =====================================================================
__device__ __forceinline__ float sigf(float x) { return 1.f / (1.f + expf(-x)); }

__device__ __forceinline__ ull pk2(float v) {
    ull r; asm("mov.b64 %0, {%1, %1};" : "=l"(r) : "f"(v)); return r;
}
__device__ __forceinline__ void upk(ull v, float& lo, float& hi) {
    asm("mov.b64 {%0, %1}, %2;" : "=f"(lo), "=f"(hi) : "l"(v));
}
__device__ __forceinline__ void fma2(ull& d, ull a, ull b) {
    asm("fma.rn.f32x2 %0, %1, %2, %0;" : "+l"(d) : "l"(a), "l"(b));
}

__device__ __forceinline__ void st_rel(unsigned* p, unsigned v) {
    asm volatile("{ .reg .u64 a; cvta.to.global.u64 a, %0; st.release.gpu.global.u32 [a], %1; }"
                 :: "l"(p), "r"(v) : "memory");
}
__device__ __forceinline__ unsigned ld_rlx(const unsigned* p) {
    unsigned v;
    asm volatile("{ .reg .u64 a; cvta.to.global.u64 a, %1; ld.relaxed.gpu.global.u32 %0, [a]; }"
                 : "=r"(v) : "l"(p) : "memory");
    return v;
}
__device__ __forceinline__ void spin_ge(const unsigned* p, unsigned r) {
    while (ld_rlx(p) < r) { }
}
__device__ __forceinline__ void red_add(float* p, float v) {
    asm volatile("{ .reg .u64 a; cvta.to.global.u64 a, %0; red.global.add.f32 [a], %1; }"
                 :: "l"(p), "f"(v) : "memory");
}
__device__ __forceinline__ void atom_arrive(unsigned* p, unsigned v) {
    unsigned d;
    asm volatile("{ .reg .u64 a; cvta.to.global.u64 a, %1; atom.release.gpu.global.add.u32 %0, [a], %2; }"
                 : "=r"(d) : "l"(p), "r"(v) : "memory");
}

// staging copy: cp.async.cg — L1 bypass global->shared
__device__ __forceinline__ void copy4(float* dst, const float* src, int nfl)
{
    unsigned base = (unsigned)__cvta_generic_to_shared(dst);
    int n4 = nfl >> 2;
    for (int i = threadIdx.x; i < n4; i += NTH) {
        asm volatile("cp.async.cg.shared.global [%0], [%1], 16;"
                     :: "r"(base + i*16), "l"((const char*)src + i*16) : "memory");
    }
}
__device__ __forceinline__ void cpwait()
{
    asm volatile("cp.async.commit_group;" ::: "memory");
    asm volatile("cp.async.wait_group 0;" ::: "memory");
    __syncthreads();
}

// K-transposed accumulate, k-major weights
__device__ __forceinline__ void accT8(ull a01[8], ull a23[8],
                                      unsigned wbyte, unsigned vbyte, int k0, int k1, int b)
{
    unsigned va = vbyte + b*4 + k0*(NB*4);
    unsigned wa = wbyte + k0*128;
#pragma unroll 2
    for (int k = k0; k < k1; k++) {
        float hv;
        asm("ld.shared.b32 %0, [%1];" : "=f"(hv) : "r"(va));
        ull hh = pk2(hv);
#pragma unroll
        for (int u = 0; u < 8; u++) {
            ull wx, wy;
            asm("ld.shared.v2.b64 {%0,%1}, [%2];" : "=l"(wx), "=l"(wy) : "r"(wa + u*16));
            fma2(a01[u], wx, hh);
            fma2(a23[u], wy, hh);
        }
        va += NB*4; wa += 128;
    }
}

__device__ __forceinline__ void accT4(ull a01[4], ull a23[4],
                                      unsigned wbyte, unsigned vbyte, int k0, int k1, int b)
{
    unsigned va = vbyte + b*4 + k0*(NB*4);
    unsigned wa = wbyte + k0*64;
#pragma unroll 2
    for (int k = k0; k < k1; k++) {
        float hv;
        asm("ld.shared.b32 %0, [%1];" : "=f"(hv) : "r"(va));
        ull hh = pk2(hv);
#pragma unroll
        for (int u = 0; u < 4; u++) {
            ull wx, wy;
            asm("ld.shared.v2.b64 {%0,%1}, [%2];" : "=l"(wx), "=l"(wy) : "r"(wa + u*16));
            fma2(a01[u], wx, hh);
            fma2(a23[u], wy, hh);
        }
        va += NB*4; wa += 64;
    }
}

__device__ __forceinline__ void store_red8(float* s_red, int wib, int b,
                                           const ull a01[8], const ull a23[8])
{
    float* rp = s_red + wib*1024 + b;
#pragma unroll
    for (int u = 0; u < 8; u++) {
        float gi,gf,gg,go;
        upk(a01[u], gi, gf); upk(a23[u], gg, go);
        rp[u*128+0]=gi; rp[u*128+32]=gf; rp[u*128+64]=gg; rp[u*128+96]=go;
    }
}
__device__ __forceinline__ void store_red4(float* s_red, int wib, int b,
                                           const ull a01[4], const ull a23[4])
{
    float* rp = s_red + wib*512 + b;
#pragma unroll
    for (int u = 0; u < 4; u++) {
        float gi,gf,gg,go;
        upk(a01[u], gi, gf); upk(a23[u], gg, go);
        rp[u*128+0]=gi; rp[u*128+32]=gf; rp[u*128+64]=gg; rp[u*128+96]=go;
    }
}

__device__ __forceinline__ float red_sum(const float* s_red, int wstr, int us, int goff, int b)
{
    float s = 0.f;
#pragma unroll
    for (int w = 0; w < 8; w++) s += s_red[w*wstr + us*128 + goff + b];
    return s;
}

// =====================================================================
// persistent RNN kernel — dataflow + distributed attention
// =====================================================================
__global__ void __launch_bounds__(NTH, 1)
rnn_kernel(const float* __restrict__ strokes,
           const int*   __restrict__ chars,
           const int*   __restrict__ lens,
           const float* __restrict__ b0, const float* __restrict__ p0,
           const float* __restrict__ b1, const float* __restrict__ p1,
           const float* __restrict__ b2, const float* __restrict__ p2,
           const float* __restrict__ Watt, const float* __restrict__ batt,
           const float* __restrict__ Wmdn, const float* __restrict__ bmdn,
           float* __restrict__ out)
{
    extern __shared__ float smem[];
    float* s_cat  = smem + OFF_CAT;
    float* s_red  = smem + OFF_RED;
    float* s_att  = smem + OFF_ATT;
    float* s_wau  = smem + OFF_WAU;
    float* s_kap  = smem + OFF_KAP;
    const unsigned sb = (unsigned)__cvta_generic_to_shared(smem);

    const int cta  = blockIdx.x;
    const int tid  = threadIdx.x;
    const int lane = tid & 31;
    const int wib  = tid >> 5;
    const int b    = lane;
    const unsigned FULL = 0xffffffffu;

    // ---- preload weight slices ----
    if (cta < 50) {
        copy4(smem + OFF_P0,  (const float*)(d_Q0  + cta*476*8), 476*8*4);
        copy4(smem + OFF_P1H, (const float*)(d_Q1h + cta*400*8), 400*8*4);
        copy4(smem + OFF_P1W, (const float*)(d_Q1w + cta*73*8),  73*8*4);
        copy4(s_wau, Watt + cta*8*30, 240);
    } else {
        const float4* prsrc = (cta < 100) ? (d_Q1r + (cta-50)*403*8)
                                          : (d_Q2r + (cta-100)*403*8);
        copy4(smem + OFF_PR,   (const float*)prsrc, 403*8*4);
        copy4(smem + OFF_P2WH, (const float*)(d_Q2wh + (cta-50)*473*4), 473*4*4);
    }
    cpwait();
    if (cta >= 100 && cta < 104) {
        if (tid < 80) s_kap[tid] = 0.f;
        __syncthreads();
    }

    float c1reg = 0.f, c2reg = 0.f;  // A: unit = cta*8+wib
    float c3reg = 0.f;               // S4 CTAs (>=50), wib<4: unit = (cta-50)*4+wib

    for (int t = 0; t < NT; t++) {
        const int p = t & 1, q = p ^ 1;
        const unsigned rt = (unsigned)t, rt1 = (unsigned)(t+1);
        const int iu = t >> 1;

        if (cta < 50) {
            // ================= A: S1 =================
            if (tid < 50) spin_ge(d_fh1 + tid*SLOT, rt);
            else if (tid < 54) spin_ge(d_fw + (tid-50)*SLOT, rt);
            else if (tid < 58) spin_ge(d_aclean + (p*4 + tid-54)*SLOT, (unsigned)(iu+1));
            __syncthreads();
            if (tid < 96) s_cat[tid] = __ldg(strokes + ((tid & 31)*NT + t)*3 + (tid >> 5));
            copy4(s_cat + 96,   d_wTb[q], NC*NB);
            copy4(s_cat + 2432, d_h1[q],  NU*NB);
            cpwait();
            float hvS1;
            {
                ull a01[8] = {0,0,0,0,0,0,0,0}, a23[8] = {0,0,0,0,0,0,0,0};
                int k0 = (476*wib) >> 3, k1 = (476*(wib+1)) >> 3;
                accT8(a01, a23, sb + OFF_P0*4, sb + OFF_CAT*4, k0, k1, b);
                store_red8(s_red, wib, b, a01, a23);
            }
            __syncthreads();
            {
                int uu = cta*8 + wib;
                float zi = __ldg(b0+uu)      + red_sum(s_red, 1024, wib, 0,  b);
                float zf = __ldg(b0+NU+uu)   + red_sum(s_red, 1024, wib, 32, b);
                float zg = __ldg(b0+2*NU+uu) + red_sum(s_red, 1024, wib, 64, b);
                float zo = __ldg(b0+3*NU+uu) + red_sum(s_red, 1024, wib, 96, b);
                float ig = sigf(zi + __ldg(p0+uu)      * c1reg);
                float fg = sigf(zf + __ldg(p0+NU+uu)   * c1reg);
                float cn = fg*c1reg + ig*tanhf(zg);
                float og = sigf(zo + __ldg(p0+2*NU+uu) * cn);
                c1reg = cn;
                hvS1 = og * tanhf(cn);
                __stcg(&d_h1[p][cta*8*NB + wib*NB + b], hvS1);
            }
            __syncthreads();
            // post h1 + distributed attention partial for this CTA's 8 units
            if (tid == 0) st_rel(d_fh1 + cta*SLOT, rt1);
            {
                float* rp2 = s_red + wib*960;
#pragma unroll
                for (int j = 0; j < 30; j++)
                    rp2[j*32 + b] = s_wau[wib*30 + j] * hvS1;
            }
            __syncthreads();
            for (int e = tid; e < 960; e += NTH) {
                float s = 0.f;
#pragma unroll
                for (int w = 0; w < 8; w++) s += s_red[w*960 + e];
                red_add(&d_attacc[p][e], s);
            }
            __syncthreads();
            if (tid == 0) atom_arrive(d_acnt + p*SLOT, 1u);

            // ================= A: S2/3 =================
            if (tid < 50) spin_ge(d_fh1 + tid*SLOT, rt1);
            __syncthreads();
            copy4(s_cat, d_h1[p], NU*NB);   // h1[t] at cat[0:12800]
            cpwait();
            {
                ull a01[8] = {0,0,0,0,0,0,0,0}, a23[8] = {0,0,0,0,0,0,0,0};
                int k0 = wib*50, k1 = k0 + 50;
                accT8(a01, a23, sb + OFF_P1H*4, sb + OFF_CAT*4, k0, k1, b);
                if (tid < 4) spin_ge(d_fw + tid*SLOT, rt1);
                if (tid == 4) spin_ge(d_fz + cta*SLOT, rt1);
                __syncthreads();
                copy4(s_cat + 12800, d_wTb[p], NC*NB);   // w[t]
                cpwait();
                int kw0 = (73*wib) >> 3, kw1 = (73*(wib+1)) >> 3;
                accT8(a01, a23, sb + OFF_P1W*4, sb + (OFF_CAT+12800)*4, kw0, kw1, b);
                store_red8(s_red, wib, b, a01, a23);
            }
            __syncthreads();
            {
                int uu = cta*8 + wib;
                const float* zp = d_Z2pb[p] + uu*128 + b;
                float zi = __ldcg(zp)    + red_sum(s_red, 1024, wib, 0,  b);
                float zf = __ldcg(zp+32) + red_sum(s_red, 1024, wib, 32, b);
                float zg = __ldcg(zp+64) + red_sum(s_red, 1024, wib, 64, b);
                float zo = __ldcg(zp+96) + red_sum(s_red, 1024, wib, 96, b);
                float ig = sigf(zi + __ldg(p1+uu)      * c2reg);
                float fg = sigf(zf + __ldg(p1+NU+uu)   * c2reg);
                float cn = fg*c2reg + ig*tanhf(zg);
                float og = sigf(zo + __ldg(p1+2*NU+uu) * cn);
                c2reg = cn;
                __stcg(&d_h2b[p][uu*NB + b], og * tanhf(cn));
            }
            __syncthreads();
            if (tid == 0) st_rel(d_fh2 + cta*SLOT, rt1);
        } else {
            // ---- finalize attention (CTAs 100-103), FIRST: shortest w path ----
            if (cta >= 100 && cta < 104) {
                int fc = cta - 100;
                if (tid == 0) spin_ge(d_acnt + p*SLOT, 50u*(unsigned)(iu+1));
                __syncthreads();
                int ab = fc*8 + wib;
                float att = 0.f;
                if (lane < 30) att = __ldg(batt + lane) + __ldcg(&d_attacc[p][lane*NB + ab]);
                float ah = __shfl_sync(FULL, att, (lane < 10) ? lane      : 0);
                float bh = __shfl_sync(FULL, att, (lane < 10) ? lane + 10 : 10);
                float kh = __shfl_sync(FULL, att, (lane < 10) ? lane + 20 : 20);
                float alpha = 0.f, beta = 0.f, kap = 0.f;
                if (lane < 10) {
                    alpha = expf(ah);
                    beta  = expf(bh);
                    kap   = s_kap[wib*10 + lane] + expf(kh);
                    s_kap[wib*10 + lane] = kap;
                }
                float* sw = s_att + wib*76;
                for (int c = lane; c < NC; c += 32) sw[c] = 0.f;
                __syncwarp();
                int lb = __ldg(lens + ab);
#pragma unroll
                for (int hh = 0; hh < 2; hh++) {
                    int uu = lane + hh*32;
                    float phi = 0.f;
#pragma unroll
                    for (int g = 0; g < NKG; g++) {
                        float ag = __shfl_sync(FULL, alpha, g);
                        float bg = __shfl_sync(FULL, beta,  g);
                        float kg = __shfl_sync(FULL, kap,   g);
                        float df = kg - (float)uu;
                        phi = fmaf(ag, expf(-bg*df*df), phi);
                    }
                    if (uu < NUC && uu < lb) {
                        int c = __ldg(chars + ab*NUC + uu);
                        atomicAdd(&sw[c], phi);
                    }
                }
                __syncwarp();
                for (int c = lane; c < NC; c += 32) __stcg(&d_wTb[p][c*NB + ab], sw[c]);
                __syncthreads();
                if (tid == 0) st_rel(d_fw + fc*SLOT, rt1);
                // zero our attacc columns, post clean (WAR backpressure, 2-step slack)
                for (int e = tid; e < 240; e += NTH) {
                    int j = e >> 3, s8 = e & 7;
                    __stcg(&d_attacc[p][j*NB + fc*8 + s8], 0.f);
                }
                __syncthreads();
                if (tid == 0) st_rel(d_aclean + (p*4 + fc)*SLOT, (unsigned)(iu+2));
            }

            if (cta < 100) {
                // ================= B: R2 =================
                if (tid < 50) spin_ge(d_fh2 + tid*SLOT, rt);
                __syncthreads();
                if (tid < 96) s_cat[tid] = __ldg(strokes + ((tid & 31)*NT + t)*3 + (tid >> 5));
                copy4(s_cat + 96, d_h2b[q], NU*NB);
                cpwait();
                {
                    ull a01[8] = {0,0,0,0,0,0,0,0}, a23[8] = {0,0,0,0,0,0,0,0};
                    int k0 = (403*wib) >> 3, k1 = (403*(wib+1)) >> 3;
                    accT8(a01, a23, sb + OFF_PR*4, sb + OFF_CAT*4, k0, k1, b);
                    store_red8(s_red, wib, b, a01, a23);
                }
                __syncthreads();
                {
                    int uu = (cta-50)*8 + wib;
                    float* dp = d_Z2pb[p] + uu*128 + b;
                    __stcg(dp+0,  __ldg(b1+uu)      + red_sum(s_red, 1024, wib, 0,  b));
                    __stcg(dp+32, __ldg(b1+NU+uu)   + red_sum(s_red, 1024, wib, 32, b));
                    __stcg(dp+64, __ldg(b1+2*NU+uu) + red_sum(s_red, 1024, wib, 64, b));
                    __stcg(dp+96, __ldg(b1+3*NU+uu) + red_sum(s_red, 1024, wib, 96, b));
                }
                __syncthreads();
                if (tid == 0) st_rel(d_fz + (cta-50)*SLOT, rt1);
            } else {
                // ================= C: R3 =================
                if (tid < 100) spin_ge(d_fh3 + tid*SLOT, rt);
                __syncthreads();
                if (tid < 96) s_cat[tid] = __ldg(strokes + ((tid & 31)*NT + t)*3 + (tid >> 5));
                copy4(s_cat + 96, d_h3b[q], NU*NB);
                cpwait();
                {
                    ull a01[8] = {0,0,0,0,0,0,0,0}, a23[8] = {0,0,0,0,0,0,0,0};
                    int k0 = (403*wib) >> 3, k1 = (403*(wib+1)) >> 3;
                    accT8(a01, a23, sb + OFF_PR*4, sb + OFF_CAT*4, k0, k1, b);
                    store_red8(s_red, wib, b, a01, a23);
                }
                __syncthreads();
                {
                    int uu = (cta-100)*8 + wib;
                    float* dp = d_R3pb[p] + uu*128 + b;
                    __stcg(dp+0,  __ldg(b2+uu)      + red_sum(s_red, 1024, wib, 0,  b));
                    __stcg(dp+32, __ldg(b2+NU+uu)   + red_sum(s_red, 1024, wib, 32, b));
                    __stcg(dp+64, __ldg(b2+2*NU+uu) + red_sum(s_red, 1024, wib, 64, b));
                    __stcg(dp+96, __ldg(b2+3*NU+uu) + red_sum(s_red, 1024, wib, 96, b));
                }
                __syncthreads();
                if (tid == 0) st_rel(d_fr + (cta-100)*SLOT, rt1);
            }

            // ================= common S4 (CTAs 50-149) =================
            if (tid < 50) spin_ge(d_fh2 + tid*SLOT, rt1);
            else if (tid < 54) spin_ge(d_fw + (tid-50)*SLOT, rt1);
            else if (tid == 54) spin_ge(d_fr + ((cta-50)>>1)*SLOT, rt1);
            __syncthreads();
            copy4(s_cat,        d_wTb[p], NC*NB);
            copy4(s_cat + 2336, d_h2b[p], NU*NB);
            cpwait();
            {
                ull a01[4] = {0,0,0,0}, a23[4] = {0,0,0,0};
                int k0 = (473*wib) >> 3, k1 = (473*(wib+1)) >> 3;
                accT4(a01, a23, sb + OFF_P2WH*4, sb + OFF_CAT*4, k0, k1, b);
                store_red4(s_red, wib, b, a01, a23);
            }
            __syncthreads();
            if (wib < 4) {
                int uu = (cta-50)*4 + wib;
                const float* rr = d_R3pb[p] + uu*128 + b;
                float zi = __ldcg(rr)    + red_sum(s_red, 512, wib, 0,  b);
                float zf = __ldcg(rr+32) + red_sum(s_red, 512, wib, 32, b);
                float zg = __ldcg(rr+64) + red_sum(s_red, 512, wib, 64, b);
                float zo = __ldcg(rr+96) + red_sum(s_red, 512, wib, 96, b);
                float ig = sigf(zi + __ldg(p2+uu)      * c3reg);
                float fg = sigf(zf + __ldg(p2+NU+uu)   * c3reg);
                float cn = fg*c3reg + ig*tanhf(zg);
                float og = sigf(zo + __ldg(p2+2*NU+uu) * cn);
                c3reg = cn;
                float hv = og * tanhf(cn);
                __stcg(&d_h3b[p][uu*NB + b], hv);
                __stcg(&d_h3all[(t*NU + uu)*NB + b], hv);
            }
            __syncthreads();
            if (tid == 0) st_rel(d_fh3 + (cta-50)*SLOT, rt1);
        }
    }

    // ================= MDN head =================
    if (tid < 100) spin_ge(d_fh3 + tid*SLOT, (unsigned)NT);
    __syncthreads();

    const int gw = cta*NWARP + wib;
    const int NW = NCTA*NWARP;
    for (int task = gw; task < NB*NT; task += NW) {
        int bb = task / NT;
        int tt = task - bb*NT;
        const float* h3p = d_h3all + (tt*NU)*NB + bb;

        int j0 = lane, j1 = lane + 32, j2 = lane + 64, j3 = lane + 96;
        float a0 = __ldg(bmdn + j0);
        float a1 = __ldg(bmdn + j1);
        float a2 = __ldg(bmdn + j2);
        float a3 = (j3 < NO) ? __ldg(bmdn + j3) : 0.f;
#pragma unroll 4
        for (int k = 0; k < NU; k++) {
            float hv = __ldcg(h3p + k*NB);
            const float* wr = Wmdn + k*NO;
            a0 = fmaf(hv, __ldg(wr + j0), a0);
            a1 = fmaf(hv, __ldg(wr + j1), a1);
            a2 = fmaf(hv, __ldg(wr + j2), a2);
            a3 = fmaf(hv, (j3 < NO) ? __ldg(wr + j3) : 0.f, a3);
        }
        float v = (lane < 20) ? a0 : -INFINITY;
#pragma unroll
        for (int off = 16; off > 0; off >>= 1) v = fmaxf(v, __shfl_xor_sync(FULL, v, off));
        float e = (lane < 20) ? expf(a0 - v) : 0.f;
        float s = e;
#pragma unroll
        for (int off = 16; off > 0; off >>= 1) s += __shfl_xor_sync(FULL, s, off);

        float* op = out + (bb*NT + tt)*NO;
        op[j0] = (lane < 20) ? (e / s) : a0;       // pi | mu1
        op[j1] = (j1 >= 60) ? expf(a1) : a1;       // mu | s1(60-63)
        op[j2] = expf(a2);                         // s1/s2
        if (j3 < NO) {
            float o3;
            if (j3 < 100)      o3 = expf(a3);      // s2
            else if (j3 < 120) o3 = tanhf(a3);     // rho
            else               o3 = sigf(a3);      // eos
            op[j3] = o3;
        }
    }
}

// =====================================================================
// launch
// =====================================================================
extern "C" void kernel_launch(void* const* d_in, const int* in_sizes, int n_in,
                              void* d_out, int out_size)
{
    const float* strokes = (const float*)d_in[0];
    const int*   chars   = (const int*)  d_in[1];
    const int*   lens    = (const int*)  d_in[2];
    const float* Wx0 = (const float*)d_in[3];
    const float* Wh0 = (const float*)d_in[4];
    const float* b0  = (const float*)d_in[5];
    const float* p0  = (const float*)d_in[6];
    const float* Wx1 = (const float*)d_in[7];
    const float* Wh1 = (const float*)d_in[8];
    const float* b1  = (const float*)d_in[9];
    const float* p1  = (const float*)d_in[10];
    const float* Wx2 = (const float*)d_in[11];
    const float* Wh2 = (const float*)d_in[12];
    const float* b2  = (const float*)d_in[13];
    const float* p2  = (const float*)d_in[14];
    const float* Watt = (const float*)d_in[15];
    const float* batt = (const float*)d_in[16];
    const float* Wmdn = (const float*)d_in[17];
    const float* bmdn = (const float*)d_in[18];
    float* out = (float*)d_out;

    static int smem_set = 0;
    if (!smem_set) {
        cudaFuncSetAttribute(rnn_kernel, cudaFuncAttributeMaxDynamicSharedMemorySize, SMEM_BYTES);
        smem_set = 1;
    }

    pack_kernel<<<256, 256>>>(Wx0, Wh0, Wx1, Wh1, Wx2, Wh2);
    rnn_kernel<<<NCTA, NTH, SMEM_BYTES>>>(strokes, chars, lens,
                                          b0, p0, b1, p1, b2, p2,
                                          Watt, batt, Wmdn, bmdn, out);
}